// round 7
// baseline (speedup 1.0000x reference)
#include <cuda_runtime.h>
#include <math.h>

#define B_ 512
#define C_ 64
#define H_ 128
#define P_ 16
#define G_ 2
#define EPS_ 1e-5f

typedef unsigned long long u64;

__device__ __forceinline__ u64 fma2(u64 a, u64 b, u64 c) {
    u64 d;
    asm("fma.rn.f32x2 %0, %1, %2, %3;" : "=l"(d) : "l"(a), "l"(b), "l"(c));
    return d;
}
__device__ __forceinline__ u64 pack2(float lo, float hi) {
    u64 d; asm("mov.b64 %0, {%1, %2};" : "=l"(d) : "f"(lo), "f"(hi)); return d;
}
__device__ __forceinline__ float2 unpack2(u64 v) {
    float2 r; asm("mov.b64 {%0, %1}, %2;" : "=f"(r.x), "=f"(r.y) : "l"(v)); return r;
}

// ---------------- device scratch ----------------
__device__ float  g_ec[C_ * H_];      // layernormed emb_column
__device__ float  g_hp[P_ * H_];      // ep @ W1^T + lin_b + ep
__device__ float  g_F[C_ * H_];       // F[c][k] = ec[c][k] + sum_h W2[h][k]*ec[c][h]
__device__ float  g_hpc[P_ * C_];     // hpc[p][c] = sum_h hp[p][h]*ec[c][h]
__device__ float4 g_pc[P_];           // {|w|, max(-w,0), gn_w, gn_b}
__device__ float  g_gc[2 * 4];        // per-group {A1,A2,B1,B2}

// ---------------- K1a: setup stage 1 (5 blocks, 512 threads) ----------------
__global__ __launch_bounds__(512)
void setup1_kernel(const float* __restrict__ emb_column,
                   const float* __restrict__ emb_prompt,
                   const float* __restrict__ lin_w,
                   const float* __restrict__ lin_b,
                   const float* __restrict__ ln_col_w,
                   const float* __restrict__ ln_col_b,
                   const float* __restrict__ ln_pr_w,
                   const float* __restrict__ ln_pr_b,
                   const float* __restrict__ expand_weight,
                   const float* __restrict__ gn_w,
                   const float* __restrict__ gn_b)
{
    __shared__ float s_ep[4][H_];
    __shared__ float s_t[H_ * 33];

    const int tid  = threadIdx.x;
    const int warp = tid >> 5;
    const int lane = tid & 31;
    const int bid  = blockIdx.x;

    if (bid == 4) {
        // layernorm emb_column -> g_ec
        for (int r = warp; r < C_; r += 16) {
            const float* src = emb_column + r * H_;
            float v[4]; float s = 0.f, ss = 0.f;
            #pragma unroll
            for (int i = 0; i < 4; i++) { v[i] = src[lane + 32 * i]; s += v[i]; ss += v[i] * v[i]; }
            #pragma unroll
            for (int o = 16; o > 0; o >>= 1) {
                s  += __shfl_xor_sync(0xffffffffu, s,  o);
                ss += __shfl_xor_sync(0xffffffffu, ss, o);
            }
            const float mu  = s * (1.f / H_);
            const float inv = rsqrtf(ss * (1.f / H_) - mu * mu + EPS_);
            #pragma unroll
            for (int i = 0; i < 4; i++) {
                const int h = lane + 32 * i;
                g_ec[r * H_ + h] = (v[i] - mu) * inv * ln_col_w[h] + ln_col_b[h];
            }
        }
        return;
    }

    // ---- hp blocks (bid 0..3): prompts p0..p0+3
    const int p0 = bid * 4;
    if (warp < 4) {
        const int r = warp;
        const float* src = emb_prompt + (p0 + r) * H_;
        float v[4]; float s = 0.f, ss = 0.f;
        #pragma unroll
        for (int i = 0; i < 4; i++) { v[i] = src[lane + 32 * i]; s += v[i]; ss += v[i] * v[i]; }
        #pragma unroll
        for (int o = 16; o > 0; o >>= 1) {
            s  += __shfl_xor_sync(0xffffffffu, s,  o);
            ss += __shfl_xor_sync(0xffffffffu, ss, o);
        }
        const float mu  = s * (1.f / H_);
        const float inv = rsqrtf(ss * (1.f / H_) - mu * mu + EPS_);
        #pragma unroll
        for (int i = 0; i < 4; i++) {
            const int h = lane + 32 * i;
            s_ep[r][h] = (v[i] - mu) * inv * ln_pr_w[h] + ln_pr_b[h];
        }
    }
    __syncthreads();

    {
        const int h = tid & 127;
        const int j = tid >> 7;
        float acc = lin_b[h] + s_ep[j][h];
        for (int kt = 0; kt < H_; kt += 32) {
            #pragma unroll
            for (int i = 0; i < 8; i++) {
                const int idx = tid + i * 512;       // 128h x 32k
                const int hh = idx >> 5, kk = idx & 31;
                s_t[hh * 33 + kk] = lin_w[hh * (2 * H_) + kt + kk];
            }
            __syncthreads();
            #pragma unroll
            for (int j2 = 0; j2 < 32; j2++)
                acc += s_t[h * 33 + j2] * s_ep[j][kt + j2];
            __syncthreads();
        }
        g_hp[(p0 + j) * H_ + h] = acc;
    }

    if (bid == 0 && tid == 0) {
        #pragma unroll
        for (int p = 0; p < P_; p++) {
            const float w = expand_weight[p];
            g_pc[p] = make_float4(fabsf(w), fmaxf(-w, 0.f), gn_w[p], gn_b[p]);
        }
        for (int g = 0; g < 2; g++) {
            float A1 = 0.f, A2 = 0.f, B1 = 0.f, B2 = 0.f;
            for (int p = g * 8; p < g * 8 + 8; p++) {
                const float w  = expand_weight[p];
                const float aw = fabsf(w);
                const float v  = fmaxf(-w, 0.f);
                const float u  = aw - v;
                A1 += aw; A2 += v; B1 += u * u; B2 += v * v;
            }
            g_gc[g * 4 + 0] = A1; g_gc[g * 4 + 1] = A2;
            g_gc[g * 4 + 2] = B1; g_gc[g * 4 + 3] = B2;
        }
    }
}

// ---------------- K1b: setup stage 2 — F and hpc (64 blocks = c, 128 threads = k) ----
__global__ __launch_bounds__(128)
void setup2_kernel(const float* __restrict__ lin_w)
{
    __shared__ float s_ecrow[H_];
    const int c   = blockIdx.x;
    const int tid = threadIdx.x;

    s_ecrow[tid] = g_ec[c * H_ + tid];
    __syncthreads();

    // G[k=tid][c] = sum_h W2[h][k] * ec[c][h];  W2[h][k] = lin_w[h*2H + H + k]
    float g = 0.f;
    #pragma unroll 4
    for (int h = 0; h < H_; h++)
        g += lin_w[h * (2 * H_) + H_ + tid] * s_ecrow[h];
    g_F[c * H_ + tid] = g + s_ecrow[tid];

    // hpc[p][c] = sum_h hp[p][h] * ec[c][h]
    if (tid < P_) {
        float a = 0.f;
        #pragma unroll 4
        for (int h = 0; h < H_; h++)
            a += g_hp[tid * H_ + h] * s_ecrow[h];
        g_hpc[tid * C_ + c] = a;
    }
}

// ---------------- K2: fused per-batch kernel (512 blocks, 512 threads) ----------------
// smem (floats): x[64x128] | F[64x132] | p2[2][16][64] (mt[64x20] aliased at p2 base) | red | grp
#define SM_X     0                        // 8192
#define SM_F     (64 * 128)               // 8448
#define SM_P2    (SM_F + 64 * 132)        // 2048
#define SM_MT    SM_P2                    // alias (guarded by __syncthreads)
#define SM_RED   (SM_P2 + 2048)           // 64
#define SM_GRP   (SM_RED + 64)            // 8
#define SM_FLOATS (SM_GRP + 8)            // 18760 floats = 75,040 B

extern __shared__ float sm[];

__global__ void __launch_bounds__(512, 2)
trompt_main_kernel(const float* __restrict__ x,
                   const float* __restrict__ x_prompt,
                   float* __restrict__ out)
{
    float* s_x   = sm + SM_X;
    float* s_F   = sm + SM_F;
    float* s_p2  = sm + SM_P2;
    float* s_mt  = sm + SM_MT;
    float* s_red = sm + SM_RED;
    float* s_grp = sm + SM_GRP;

    const int tid  = threadIdx.x;
    const int b    = blockIdx.x;
    const int warp = tid >> 5;
    const int lane = tid & 31;

    // ---- loads + fused batch stats
    {
        float s1 = 0.f, sx = 0.f, sr2 = 0.f, sx2 = 0.f;
        const float4* xb4 = (const float4*)(x + (size_t)b * (C_ * H_));
        #pragma unroll
        for (int i = 0; i < 4; i++) {
            const float4 v = xb4[tid + i * 512];
            *(float4*)(s_x + (tid + i * 512) * 4) = v;
            float vv[4] = {v.x, v.y, v.z, v.w};
            #pragma unroll
            for (int q = 0; q < 4; q++) {
                const float r = fmaxf(vv[q], 0.f);
                s1 += r; sx += vv[q]; sr2 += r * r; sx2 += vv[q] * vv[q];
            }
        }
        const float4* f4 = (const float4*)g_F;
        #pragma unroll
        for (int i = 0; i < 4; i++) {
            const int e = tid + i * 512;
            const float4 v = f4[e];
            const int idx = e * 4;
            *(float4*)(s_F + (idx >> 7) * 132 + (idx & 127)) = v;
        }

        #pragma unroll
        for (int o = 16; o > 0; o >>= 1) {
            s1  += __shfl_xor_sync(0xffffffffu, s1,  o);
            sx  += __shfl_xor_sync(0xffffffffu, sx,  o);
            sr2 += __shfl_xor_sync(0xffffffffu, sr2, o);
            sx2 += __shfl_xor_sync(0xffffffffu, sx2, o);
        }
        if (lane == 0) {
            s_red[warp * 4 + 0] = s1;  s_red[warp * 4 + 1] = sx;
            s_red[warp * 4 + 2] = sr2; s_red[warp * 4 + 3] = sx2;
        }
    }
    __syncthreads();

    // ---- phase M: m[p,c] partials = xp @ F^T ; thread = (c, pg of 4p, hs h-half)
    {
        const int c  = tid & 63;
        const int pg = (tid >> 6) & 3;
        const int hs = tid >> 8;
        const int p0 = pg * 4;
        const int hb = hs * 64;
        const float* xpg = x_prompt + (size_t)b * (P_ * H_);
        u64 aa[4] = {0,0,0,0}, ab[4] = {0,0,0,0};
        #pragma unroll
        for (int hh = 0; hh < 64; hh += 4) {
            const ulonglong2 e = *(const ulonglong2*)(s_F + c * 132 + hb + hh);
            #pragma unroll
            for (int j = 0; j < 4; j++) {
                const ulonglong2 t = *(const ulonglong2*)(xpg + (p0 + j) * H_ + hb + hh);
                aa[j] = fma2(e.x, t.x, aa[j]);
                ab[j] = fma2(e.y, t.y, ab[j]);
            }
        }
        #pragma unroll
        for (int j = 0; j < 4; j++) {
            const float2 ra = unpack2(aa[j]);
            const float2 rb = unpack2(ab[j]);
            s_p2[hs * 1024 + (p0 + j) * 64 + c] = (ra.x + ra.y) + (rb.x + rb.y);
        }
    }
    __syncthreads();

    // ---- softmax (warp = p): partials + hpc, softmax over c, store transposed s_mt[c][p]
    {
        const int p = warp;
        const float v0 = s_p2[p * 64 + lane]      + s_p2[1024 + p * 64 + lane]
                       + g_hpc[p * C_ + lane];
        const float v1 = s_p2[p * 64 + 32 + lane] + s_p2[1024 + p * 64 + 32 + lane]
                       + g_hpc[p * C_ + 32 + lane];
        __syncthreads();   // all p2 reads done before mt (aliased) writes

        float mx = fmaxf(v0, v1);
        #pragma unroll
        for (int o = 16; o > 0; o >>= 1)
            mx = fmaxf(mx, __shfl_xor_sync(0xffffffffu, mx, o));
        const float e0 = __expf(v0 - mx);
        const float e1 = __expf(v1 - mx);
        float s = e0 + e1;
        #pragma unroll
        for (int o = 16; o > 0; o >>= 1)
            s += __shfl_xor_sync(0xffffffffu, s, o);
        const float inv = 1.f / s;
        s_mt[lane * 20 + p]        = e0 * inv;
        s_mt[(lane + 32) * 20 + p] = e1 * inv;

        if (tid == 0) {
            float S1 = 0.f, Sx = 0.f, Sr2 = 0.f, Sx2 = 0.f;
            #pragma unroll
            for (int w = 0; w < 16; w++) {
                S1 += s_red[w * 4 + 0]; Sx  += s_red[w * 4 + 1];
                Sr2 += s_red[w * 4 + 2]; Sx2 += s_red[w * 4 + 3];
            }
            const float invN = 1.f / 65536.f;
            #pragma unroll
            for (int g = 0; g < 2; g++) {
                const float A1 = g_gc[g * 4 + 0], A2 = g_gc[g * 4 + 1];
                const float B1 = g_gc[g * 4 + 2], B2 = g_gc[g * 4 + 3];
                const float mu = (A1 * S1 - A2 * Sx) * invN;
                const float E2 = (B1 * Sr2 + B2 * (Sx2 - Sr2)) * invN;
                s_grp[g * 2 + 0] = mu;
                s_grp[g * 2 + 1] = rsqrtf(E2 - mu * mu + EPS_);
            }
        }
    }
    __syncthreads();

    // ---- phase 4: out[p,h]; thread = (h, pb); packed over p-pairs
    {
        const int h  = tid & 127;
        const int pb = tid >> 7;
        float c1[4], c2[4], c3[4];
        #pragma unroll
        for (int j = 0; j < 4; j++) {
            const int p = pb * 4 + j;
            const float4 pc = g_pc[p];
            const int g = p >> 3;
            const float mu = s_grp[g * 2 + 0];
            const float rs = s_grp[g * 2 + 1];
            const float gr = pc.z * rs;
            c1[j] = gr * pc.x;
            c2[j] = 1.f - gr * pc.y;
            c3[j] = pc.w - gr * mu;
        }
        u64 accR01 = 0, accR23 = 0, accX01 = 0, accX23 = 0;
        for (int c = 0; c < C_; c++) {
            const float xv = s_x[c * H_ + h];
            const float rv = fmaxf(xv, 0.f);
            const u64 rr = pack2(rv, rv);
            const u64 xx = pack2(xv, xv);
            const ulonglong2 mq = *(const ulonglong2*)(s_mt + c * 20 + pb * 4);
            accR01 = fma2(mq.x, rr, accR01);
            accR23 = fma2(mq.y, rr, accR23);
            accX01 = fma2(mq.x, xx, accX01);
            accX23 = fma2(mq.y, xx, accX23);
        }
        const float2 R01 = unpack2(accR01), R23 = unpack2(accR23);
        const float2 X01 = unpack2(accX01), X23 = unpack2(accX23);
        float* ob = out + (size_t)b * (P_ * H_);
        ob[(pb * 4 + 0) * H_ + h] = c1[0] * R01.x + c2[0] * X01.x + c3[0];
        ob[(pb * 4 + 1) * H_ + h] = c1[1] * R01.y + c2[1] * X01.y + c3[1];
        ob[(pb * 4 + 2) * H_ + h] = c1[2] * R23.x + c2[2] * X23.x + c3[2];
        ob[(pb * 4 + 3) * H_ + h] = c1[3] * R23.y + c2[3] * X23.y + c3[3];
    }
}

// ---------------- launch ----------------
extern "C" void kernel_launch(void* const* d_in, const int* in_sizes, int n_in,
                              void* d_out, int out_size)
{
    const float* x          = (const float*)d_in[0];
    const float* x_prompt   = (const float*)d_in[1];
    const float* emb_column = (const float*)d_in[2];
    const float* emb_prompt = (const float*)d_in[3];
    const float* lin_w      = (const float*)d_in[4];
    const float* lin_b      = (const float*)d_in[5];
    const float* ln_col_w   = (const float*)d_in[6];
    const float* ln_col_b   = (const float*)d_in[7];
    const float* ln_pr_w    = (const float*)d_in[8];
    const float* ln_pr_b    = (const float*)d_in[9];
    const float* expand_w   = (const float*)d_in[10];
    const float* gn_w       = (const float*)d_in[11];
    const float* gn_b       = (const float*)d_in[12];
    float* out = (float*)d_out;

    const int smemBytes = SM_FLOATS * (int)sizeof(float);   // 75,040 B
    cudaFuncSetAttribute(trompt_main_kernel,
                         cudaFuncAttributeMaxDynamicSharedMemorySize, smemBytes);

    setup1_kernel<<<5, 512>>>(emb_column, emb_prompt, lin_w, lin_b,
                              ln_col_w, ln_col_b, ln_pr_w, ln_pr_b,
                              expand_w, gn_w, gn_b);
    setup2_kernel<<<64, 128>>>(lin_w);
    trompt_main_kernel<<<B_, 512, smemBytes>>>(x, x_prompt, out);
}

// round 8
// speedup vs baseline: 1.2221x; 1.2221x over previous
#include <cuda_runtime.h>
#include <math.h>

#define B_ 512
#define C_ 64
#define H_ 128
#define P_ 16
#define G_ 2
#define EPS_ 1e-5f

typedef unsigned long long u64;

__device__ __forceinline__ u64 fma2(u64 a, u64 b, u64 c) {
    u64 d;
    asm("fma.rn.f32x2 %0, %1, %2, %3;" : "=l"(d) : "l"(a), "l"(b), "l"(c));
    return d;
}
__device__ __forceinline__ u64 pack2(float lo, float hi) {
    u64 d; asm("mov.b64 %0, {%1, %2};" : "=l"(d) : "f"(lo), "f"(hi)); return d;
}
__device__ __forceinline__ float2 unpack2(u64 v) {
    float2 r; asm("mov.b64 {%0, %1}, %2;" : "=f"(r.x), "=f"(r.y) : "l"(v)); return r;
}

// ---------------- device scratch ----------------
__device__ float  g_F[C_ * H_];       // F[c][k] = ec[c][k] + sum_h W2[h][k]*ec[c][h]
__device__ float  g_hpc[P_ * C_];     // hpc[p][c] = <lin_b+ep[p], ec[c]> + <ep[p], G1[c]>
__device__ float4 g_pc[P_];           // {|w|, max(-w,0), gn_w, gn_b}
__device__ float  g_gc[2 * 4];        // per-group {A1,A2,B1,B2}

// ---------------- K1: ONE setup kernel (64 blocks = c, 256 threads) ----------------
__global__ __launch_bounds__(256)
void setup_kernel(const float* __restrict__ emb_column,
                  const float* __restrict__ emb_prompt,
                  const float* __restrict__ lin_w,
                  const float* __restrict__ lin_b,
                  const float* __restrict__ ln_col_w,
                  const float* __restrict__ ln_col_b,
                  const float* __restrict__ ln_pr_w,
                  const float* __restrict__ ln_pr_b,
                  const float* __restrict__ expand_weight,
                  const float* __restrict__ gn_w,
                  const float* __restrict__ gn_b)
{
    __shared__ float s_ec[H_];          // layernormed ec row c
    __shared__ float s_ep[P_][H_];      // layernormed ep (all rows, redundant per block)
    __shared__ float s_G1[H_];          // G1[c][k]

    const int c    = blockIdx.x;
    const int tid  = threadIdx.x;
    const int warp = tid >> 5;
    const int lane = tid & 31;

    // ---- LN: warp 0 does ec row c; each of 8 warps does 2 ep rows
    if (warp == 0) {
        const float* src = emb_column + c * H_;
        float v[4]; float s = 0.f, ss = 0.f;
        #pragma unroll
        for (int i = 0; i < 4; i++) { v[i] = src[lane + 32 * i]; s += v[i]; ss += v[i] * v[i]; }
        #pragma unroll
        for (int o = 16; o > 0; o >>= 1) {
            s  += __shfl_xor_sync(0xffffffffu, s,  o);
            ss += __shfl_xor_sync(0xffffffffu, ss, o);
        }
        const float mu  = s * (1.f / H_);
        const float inv = rsqrtf(ss * (1.f / H_) - mu * mu + EPS_);
        #pragma unroll
        for (int i = 0; i < 4; i++) {
            const int hh = lane + 32 * i;
            s_ec[hh] = (v[i] - mu) * inv * ln_col_w[hh] + ln_col_b[hh];
        }
    }
    #pragma unroll
    for (int rr = 0; rr < 2; rr++) {
        const int r = warp + rr * 8;
        const float* src = emb_prompt + r * H_;
        float v[4]; float s = 0.f, ss = 0.f;
        #pragma unroll
        for (int i = 0; i < 4; i++) { v[i] = src[lane + 32 * i]; s += v[i]; ss += v[i] * v[i]; }
        #pragma unroll
        for (int o = 16; o > 0; o >>= 1) {
            s  += __shfl_xor_sync(0xffffffffu, s,  o);
            ss += __shfl_xor_sync(0xffffffffu, ss, o);
        }
        const float mu  = s * (1.f / H_);
        const float inv = rsqrtf(ss * (1.f / H_) - mu * mu + EPS_);
        #pragma unroll
        for (int i = 0; i < 4; i++) {
            const int hh = lane + 32 * i;
            s_ep[r][hh] = (v[i] - mu) * inv * ln_pr_w[hh] + ln_pr_b[hh];
        }
    }
    __syncthreads();

    // ---- G1 (W1 half) and G->F (W2 half): thread tid reads column (tid) of each lin_w row
    // lin_w row h has 256 floats: [0,128) = W1[h][k], [128,256) = W2[h][k].
    {
        const int k     = tid & 127;
        const int which = tid >> 7;     // 0 -> G1, 1 -> G (then F)
        float acc = 0.f;
        #pragma unroll 4
        for (int h = 0; h < H_; h++)
            acc += lin_w[h * (2 * H_) + which * H_ + k] * s_ec[h];
        if (which == 0) {
            s_G1[k] = acc;
        } else {
            g_F[c * H_ + k] = acc + s_ec[k];
        }
    }
    __syncthreads();

    // ---- hpc[p][c]: warp w handles p = w, w+8
    #pragma unroll
    for (int rr = 0; rr < 2; rr++) {
        const int p = warp + rr * 8;
        float a = 0.f;
        #pragma unroll
        for (int i = 0; i < 4; i++) {
            const int hh = lane + 32 * i;
            const float e = s_ep[p][hh];
            a += (lin_b[hh] + e) * s_ec[hh] + e * s_G1[hh];
        }
        #pragma unroll
        for (int o = 16; o > 0; o >>= 1)
            a += __shfl_xor_sync(0xffffffffu, a, o);
        if (lane == 0) g_hpc[p * C_ + c] = a;
    }

    // ---- per-prompt / per-group coefficients (block 0 only)
    if (c == 0 && tid == 0) {
        #pragma unroll
        for (int p = 0; p < P_; p++) {
            const float w = expand_weight[p];
            g_pc[p] = make_float4(fabsf(w), fmaxf(-w, 0.f), gn_w[p], gn_b[p]);
        }
        for (int g = 0; g < 2; g++) {
            float A1 = 0.f, A2 = 0.f, B1 = 0.f, B2 = 0.f;
            for (int p = g * 8; p < g * 8 + 8; p++) {
                const float w  = expand_weight[p];
                const float aw = fabsf(w);
                const float v  = fmaxf(-w, 0.f);
                const float u  = aw - v;
                A1 += aw; A2 += v; B1 += u * u; B2 += v * v;
            }
            g_gc[g * 4 + 0] = A1; g_gc[g * 4 + 1] = A2;
            g_gc[g * 4 + 2] = B1; g_gc[g * 4 + 3] = B2;
        }
    }
}

// ---------------- K2: fused per-batch kernel (512 blocks, 512 threads) ----------------
// smem (floats): x[64x128] | F[64x132] | p2[2][16][64] (mt aliased) | red | grp
#define SM_X     0                        // 8192
#define SM_F     (64 * 128)               // 8448
#define SM_P2    (SM_F + 64 * 132)        // 2048
#define SM_MT    SM_P2                    // alias (guarded by __syncthreads)
#define SM_RED   (SM_P2 + 2048)           // 64
#define SM_GRP   (SM_RED + 64)            // 8
#define SM_FLOATS (SM_GRP + 8)            // 18760 floats = 75,040 B

extern __shared__ float sm[];

__global__ void __launch_bounds__(512, 2)
trompt_main_kernel(const float* __restrict__ x,
                   const float* __restrict__ x_prompt,
                   float* __restrict__ out)
{
    float* s_x   = sm + SM_X;
    float* s_F   = sm + SM_F;
    float* s_p2  = sm + SM_P2;
    float* s_mt  = sm + SM_MT;
    float* s_red = sm + SM_RED;
    float* s_grp = sm + SM_GRP;

    const int tid  = threadIdx.x;
    const int b    = blockIdx.x;
    const int warp = tid >> 5;
    const int lane = tid & 31;

    // ---- loads + fused batch stats
    {
        float s1 = 0.f, sx = 0.f, sr2 = 0.f, sx2 = 0.f;
        const float4* xb4 = (const float4*)(x + (size_t)b * (C_ * H_));
        #pragma unroll
        for (int i = 0; i < 4; i++) {
            const float4 v = xb4[tid + i * 512];
            *(float4*)(s_x + (tid + i * 512) * 4) = v;
            float vv[4] = {v.x, v.y, v.z, v.w};
            #pragma unroll
            for (int q = 0; q < 4; q++) {
                const float r = fmaxf(vv[q], 0.f);
                s1 += r; sx += vv[q]; sr2 += r * r; sx2 += vv[q] * vv[q];
            }
        }
        const float4* f4 = (const float4*)g_F;
        #pragma unroll
        for (int i = 0; i < 4; i++) {
            const int e = tid + i * 512;
            const float4 v = f4[e];
            const int idx = e * 4;
            *(float4*)(s_F + (idx >> 7) * 132 + (idx & 127)) = v;
        }

        #pragma unroll
        for (int o = 16; o > 0; o >>= 1) {
            s1  += __shfl_xor_sync(0xffffffffu, s1,  o);
            sx  += __shfl_xor_sync(0xffffffffu, sx,  o);
            sr2 += __shfl_xor_sync(0xffffffffu, sr2, o);
            sx2 += __shfl_xor_sync(0xffffffffu, sx2, o);
        }
        if (lane == 0) {
            s_red[warp * 4 + 0] = s1;  s_red[warp * 4 + 1] = sx;
            s_red[warp * 4 + 2] = sr2; s_red[warp * 4 + 3] = sx2;
        }
    }
    __syncthreads();

    // ---- phase M: m[p,c] partials = xp @ F^T ; thread = (c, pg of 4p, hs h-half)
    {
        const int c  = tid & 63;
        const int pg = (tid >> 6) & 3;
        const int hs = tid >> 8;
        const int p0 = pg * 4;
        const int hb = hs * 64;
        const float* xpg = x_prompt + (size_t)b * (P_ * H_);
        u64 aa[4] = {0,0,0,0}, ab[4] = {0,0,0,0};
        #pragma unroll
        for (int hh = 0; hh < 64; hh += 4) {
            const ulonglong2 e = *(const ulonglong2*)(s_F + c * 132 + hb + hh);
            #pragma unroll
            for (int j = 0; j < 4; j++) {
                const ulonglong2 t = *(const ulonglong2*)(xpg + (p0 + j) * H_ + hb + hh);
                aa[j] = fma2(e.x, t.x, aa[j]);
                ab[j] = fma2(e.y, t.y, ab[j]);
            }
        }
        #pragma unroll
        for (int j = 0; j < 4; j++) {
            const float2 ra = unpack2(aa[j]);
            const float2 rb = unpack2(ab[j]);
            s_p2[hs * 1024 + (p0 + j) * 64 + c] = (ra.x + ra.y) + (rb.x + rb.y);
        }
    }
    __syncthreads();

    // ---- softmax (warp = p): partials + hpc, softmax over c, store transposed s_mt[c][p]
    {
        const int p = warp;
        const float v0 = s_p2[p * 64 + lane]      + s_p2[1024 + p * 64 + lane]
                       + g_hpc[p * C_ + lane];
        const float v1 = s_p2[p * 64 + 32 + lane] + s_p2[1024 + p * 64 + 32 + lane]
                       + g_hpc[p * C_ + 32 + lane];
        __syncthreads();   // all p2 reads done before mt (aliased) writes

        float mx = fmaxf(v0, v1);
        #pragma unroll
        for (int o = 16; o > 0; o >>= 1)
            mx = fmaxf(mx, __shfl_xor_sync(0xffffffffu, mx, o));
        const float e0 = __expf(v0 - mx);
        const float e1 = __expf(v1 - mx);
        float s = e0 + e1;
        #pragma unroll
        for (int o = 16; o > 0; o >>= 1)
            s += __shfl_xor_sync(0xffffffffu, s, o);
        const float inv = 1.f / s;
        s_mt[lane * 20 + p]        = e0 * inv;
        s_mt[(lane + 32) * 20 + p] = e1 * inv;

        if (tid == 0) {
            float S1 = 0.f, Sx = 0.f, Sr2 = 0.f, Sx2 = 0.f;
            #pragma unroll
            for (int w = 0; w < 16; w++) {
                S1 += s_red[w * 4 + 0]; Sx  += s_red[w * 4 + 1];
                Sr2 += s_red[w * 4 + 2]; Sx2 += s_red[w * 4 + 3];
            }
            const float invN = 1.f / 65536.f;
            #pragma unroll
            for (int g = 0; g < 2; g++) {
                const float A1 = g_gc[g * 4 + 0], A2 = g_gc[g * 4 + 1];
                const float B1 = g_gc[g * 4 + 2], B2 = g_gc[g * 4 + 3];
                const float mu = (A1 * S1 - A2 * Sx) * invN;
                const float E2 = (B1 * Sr2 + B2 * (Sx2 - Sr2)) * invN;
                s_grp[g * 2 + 0] = mu;
                s_grp[g * 2 + 1] = rsqrtf(E2 - mu * mu + EPS_);
            }
        }
    }
    __syncthreads();

    // ---- phase 4: out[p,h]; thread = (h, pb); packed over p-pairs
    {
        const int h  = tid & 127;
        const int pb = tid >> 7;
        float c1[4], c2[4], c3[4];
        #pragma unroll
        for (int j = 0; j < 4; j++) {
            const int p = pb * 4 + j;
            const float4 pc = g_pc[p];
            const int g = p >> 3;
            const float mu = s_grp[g * 2 + 0];
            const float rs = s_grp[g * 2 + 1];
            const float gr = pc.z * rs;
            c1[j] = gr * pc.x;
            c2[j] = 1.f - gr * pc.y;
            c3[j] = pc.w - gr * mu;
        }
        u64 accR01 = 0, accR23 = 0, accX01 = 0, accX23 = 0;
        for (int c = 0; c < C_; c++) {
            const float xv = s_x[c * H_ + h];
            const float rv = fmaxf(xv, 0.f);
            const u64 rr = pack2(rv, rv);
            const u64 xx = pack2(xv, xv);
            const ulonglong2 mq = *(const ulonglong2*)(s_mt + c * 20 + pb * 4);
            accR01 = fma2(mq.x, rr, accR01);
            accR23 = fma2(mq.y, rr, accR23);
            accX01 = fma2(mq.x, xx, accX01);
            accX23 = fma2(mq.y, xx, accX23);
        }
        const float2 R01 = unpack2(accR01), R23 = unpack2(accR23);
        const float2 X01 = unpack2(accX01), X23 = unpack2(accX23);
        float* ob = out + (size_t)b * (P_ * H_);
        ob[(pb * 4 + 0) * H_ + h] = c1[0] * R01.x + c2[0] * X01.x + c3[0];
        ob[(pb * 4 + 1) * H_ + h] = c1[1] * R01.y + c2[1] * X01.y + c3[1];
        ob[(pb * 4 + 2) * H_ + h] = c1[2] * R23.x + c2[2] * X23.x + c3[2];
        ob[(pb * 4 + 3) * H_ + h] = c1[3] * R23.y + c2[3] * X23.y + c3[3];
    }
}

// ---------------- launch ----------------
extern "C" void kernel_launch(void* const* d_in, const int* in_sizes, int n_in,
                              void* d_out, int out_size)
{
    const float* x          = (const float*)d_in[0];
    const float* x_prompt   = (const float*)d_in[1];
    const float* emb_column = (const float*)d_in[2];
    const float* emb_prompt = (const float*)d_in[3];
    const float* lin_w      = (const float*)d_in[4];
    const float* lin_b      = (const float*)d_in[5];
    const float* ln_col_w   = (const float*)d_in[6];
    const float* ln_col_b   = (const float*)d_in[7];
    const float* ln_pr_w    = (const float*)d_in[8];
    const float* ln_pr_b    = (const float*)d_in[9];
    const float* expand_w   = (const float*)d_in[10];
    const float* gn_w       = (const float*)d_in[11];
    const float* gn_b       = (const float*)d_in[12];
    float* out = (float*)d_out;

    const int smemBytes = SM_FLOATS * (int)sizeof(float);   // 75,040 B
    cudaFuncSetAttribute(trompt_main_kernel,
                         cudaFuncAttributeMaxDynamicSharedMemorySize, smemBytes);

    setup_kernel<<<64, 256>>>(emb_column, emb_prompt, lin_w, lin_b,
                              ln_col_w, ln_col_b, ln_pr_w, ln_pr_b,
                              expand_w, gn_w, gn_b);
    trompt_main_kernel<<<B_, 512, smemBytes>>>(x, x_prompt, out);
}

// round 9
// speedup vs baseline: 1.3080x; 1.0703x over previous
#include <cuda_runtime.h>
#include <math.h>

#define B_ 512
#define C_ 64
#define H_ 128
#define P_ 16
#define G_ 2
#define EPS_ 1e-5f

typedef unsigned long long u64;

__device__ __forceinline__ u64 fma2(u64 a, u64 b, u64 c) {
    u64 d;
    asm("fma.rn.f32x2 %0, %1, %2, %3;" : "=l"(d) : "l"(a), "l"(b), "l"(c));
    return d;
}
__device__ __forceinline__ u64 pack2(float lo, float hi) {
    u64 d; asm("mov.b64 %0, {%1, %2};" : "=l"(d) : "f"(lo), "f"(hi)); return d;
}
__device__ __forceinline__ float2 unpack2(u64 v) {
    float2 r; asm("mov.b64 {%0, %1}, %2;" : "=f"(r.x), "=f"(r.y) : "l"(v)); return r;
}

// ---------------- device scratch ----------------
__device__ float  g_F[C_ * H_];       // F[c][k] = ec[c][k] + sum_h W2[h][k]*ec[c][h]
__device__ float  g_hpc[P_ * C_];     // hpc[p][c]
__device__ float4 g_pc[P_];           // {|w|, max(-w,0), gn_w, gn_b}
__device__ float  g_gc[2 * 4];        // per-group {A1,A2,B1,B2}

// ---------------- K1: ONE setup kernel (64 blocks = c, 256 threads) ----------------
__global__ __launch_bounds__(256)
void setup_kernel(const float* __restrict__ emb_column,
                  const float* __restrict__ emb_prompt,
                  const float* __restrict__ lin_w,
                  const float* __restrict__ lin_b,
                  const float* __restrict__ ln_col_w,
                  const float* __restrict__ ln_col_b,
                  const float* __restrict__ ln_pr_w,
                  const float* __restrict__ ln_pr_b,
                  const float* __restrict__ expand_weight,
                  const float* __restrict__ gn_w,
                  const float* __restrict__ gn_b)
{
    __shared__ float s_ec[H_];
    __shared__ float s_ep[P_][H_];
    __shared__ float s_G1[H_];

    const int c    = blockIdx.x;
    const int tid  = threadIdx.x;
    const int warp = tid >> 5;
    const int lane = tid & 31;

    if (warp == 0) {
        const float* src = emb_column + c * H_;
        float v[4]; float s = 0.f, ss = 0.f;
        #pragma unroll
        for (int i = 0; i < 4; i++) { v[i] = src[lane + 32 * i]; s += v[i]; ss += v[i] * v[i]; }
        #pragma unroll
        for (int o = 16; o > 0; o >>= 1) {
            s  += __shfl_xor_sync(0xffffffffu, s,  o);
            ss += __shfl_xor_sync(0xffffffffu, ss, o);
        }
        const float mu  = s * (1.f / H_);
        const float inv = rsqrtf(ss * (1.f / H_) - mu * mu + EPS_);
        #pragma unroll
        for (int i = 0; i < 4; i++) {
            const int hh = lane + 32 * i;
            s_ec[hh] = (v[i] - mu) * inv * ln_col_w[hh] + ln_col_b[hh];
        }
    }
    #pragma unroll
    for (int rr = 0; rr < 2; rr++) {
        const int r = warp + rr * 8;
        const float* src = emb_prompt + r * H_;
        float v[4]; float s = 0.f, ss = 0.f;
        #pragma unroll
        for (int i = 0; i < 4; i++) { v[i] = src[lane + 32 * i]; s += v[i]; ss += v[i] * v[i]; }
        #pragma unroll
        for (int o = 16; o > 0; o >>= 1) {
            s  += __shfl_xor_sync(0xffffffffu, s,  o);
            ss += __shfl_xor_sync(0xffffffffu, ss, o);
        }
        const float mu  = s * (1.f / H_);
        const float inv = rsqrtf(ss * (1.f / H_) - mu * mu + EPS_);
        #pragma unroll
        for (int i = 0; i < 4; i++) {
            const int hh = lane + 32 * i;
            s_ep[r][hh] = (v[i] - mu) * inv * ln_pr_w[hh] + ln_pr_b[hh];
        }
    }
    __syncthreads();

    // ---- G1 / F with deep unroll (MLP=16): thread column = (which, k)
    {
        const int k     = tid & 127;
        const int which = tid >> 7;
        const float* base = lin_w + which * H_ + k;
        float acc = 0.f;
        #pragma unroll
        for (int hb = 0; hb < H_; hb += 16) {
            float w[16];
            #pragma unroll
            for (int i = 0; i < 16; i++)
                w[i] = base[(hb + i) * (2 * H_)];
            #pragma unroll
            for (int i = 0; i < 16; i++)
                acc += w[i] * s_ec[hb + i];
        }
        if (which == 0) s_G1[k] = acc;
        else            g_F[c * H_ + k] = acc + s_ec[k];
    }
    __syncthreads();

    // ---- hpc[p][c]: warp w handles p = w, w+8
    #pragma unroll
    for (int rr = 0; rr < 2; rr++) {
        const int p = warp + rr * 8;
        float a = 0.f;
        #pragma unroll
        for (int i = 0; i < 4; i++) {
            const int hh = lane + 32 * i;
            const float e = s_ep[p][hh];
            a += (lin_b[hh] + e) * s_ec[hh] + e * s_G1[hh];
        }
        #pragma unroll
        for (int o = 16; o > 0; o >>= 1)
            a += __shfl_xor_sync(0xffffffffu, a, o);
        if (lane == 0) g_hpc[p * C_ + c] = a;
    }

    if (c == 0 && tid == 0) {
        #pragma unroll
        for (int p = 0; p < P_; p++) {
            const float w = expand_weight[p];
            g_pc[p] = make_float4(fabsf(w), fmaxf(-w, 0.f), gn_w[p], gn_b[p]);
        }
        for (int g = 0; g < 2; g++) {
            float A1 = 0.f, A2 = 0.f, B1 = 0.f, B2 = 0.f;
            for (int p = g * 8; p < g * 8 + 8; p++) {
                const float w  = expand_weight[p];
                const float aw = fabsf(w);
                const float v  = fmaxf(-w, 0.f);
                const float u  = aw - v;
                A1 += aw; A2 += v; B1 += u * u; B2 += v * v;
            }
            g_gc[g * 4 + 0] = A1; g_gc[g * 4 + 1] = A2;
            g_gc[g * 4 + 2] = B1; g_gc[g * 4 + 3] = B2;
        }
    }
}

// ---------------- K2: fused per-batch kernel (512 blocks, 512 threads) ----------------
// smem (floats): F[64x132] | p2[4][16][64] (mt[64x20] aliased) | red[64] | grp[8]
#define SM_F     0                        // 8448
#define SM_P2    (64 * 132)               // 4096
#define SM_MT    SM_P2                    // alias (guarded by __syncthreads)
#define SM_RED   (SM_P2 + 4096)           // 64
#define SM_GRP   (SM_RED + 64)            // 8
#define SM_FLOATS (SM_GRP + 8)            // 12616 floats = 50,464 B

extern __shared__ float sm[];

__global__ void __launch_bounds__(512, 2)
trompt_main_kernel(const float* __restrict__ x,
                   const float* __restrict__ x_prompt,
                   float* __restrict__ out)
{
    float* s_F   = sm + SM_F;
    float* s_p2  = sm + SM_P2;
    float* s_mt  = sm + SM_MT;
    float* s_red = sm + SM_RED;
    float* s_grp = sm + SM_GRP;

    const int tid  = threadIdx.x;
    const int b    = blockIdx.x;
    const int warp = tid >> 5;
    const int lane = tid & 31;
    const float* xb = x + (size_t)b * (C_ * H_);

    // ---- F staging + batch stats over x (x stays in L1, no smem staging)
    {
        float s1 = 0.f, sx = 0.f, sr2 = 0.f, sx2 = 0.f;
        const float4* xb4 = (const float4*)xb;
        #pragma unroll
        for (int i = 0; i < 4; i++) {
            const float4 v = xb4[tid + i * 512];
            float vv[4] = {v.x, v.y, v.z, v.w};
            #pragma unroll
            for (int q = 0; q < 4; q++) {
                const float r = fmaxf(vv[q], 0.f);
                s1 += r; sx += vv[q]; sr2 += r * r; sx2 += vv[q] * vv[q];
            }
        }
        const float4* f4 = (const float4*)g_F;
        #pragma unroll
        for (int i = 0; i < 4; i++) {
            const int e = tid + i * 512;
            const float4 v = f4[e];
            const int idx = e * 4;
            *(float4*)(s_F + (idx >> 7) * 132 + (idx & 127)) = v;
        }

        #pragma unroll
        for (int o = 16; o > 0; o >>= 1) {
            s1  += __shfl_xor_sync(0xffffffffu, s1,  o);
            sx  += __shfl_xor_sync(0xffffffffu, sx,  o);
            sr2 += __shfl_xor_sync(0xffffffffu, sr2, o);
            sx2 += __shfl_xor_sync(0xffffffffu, sx2, o);
        }
        if (lane == 0) {
            s_red[warp * 4 + 0] = s1;  s_red[warp * 4 + 1] = sx;
            s_red[warp * 4 + 2] = sr2; s_red[warp * 4 + 3] = sx2;
        }
    }
    __syncthreads();

    // ---- phase M: m partials = xp @ F^T ; thread = (c, hq of 32h, pg of 8p)
    {
        const int c  = tid & 63;
        const int hq = (tid >> 6) & 3;
        const int pg = tid >> 8;
        const int p0 = pg * 8;
        const int hb = hq * 32;
        const float* xpg = x_prompt + (size_t)b * (P_ * H_);
        u64 acc[8] = {0,0,0,0,0,0,0,0};
        #pragma unroll
        for (int hh = 0; hh < 32; hh += 4) {
            const ulonglong2 e = *(const ulonglong2*)(s_F + c * 132 + hb + hh);
            #pragma unroll
            for (int j = 0; j < 8; j++) {
                const ulonglong2 t = *(const ulonglong2*)(xpg + (p0 + j) * H_ + hb + hh);
                acc[j] = fma2(e.x, t.x, acc[j]);
                acc[j] = fma2(e.y, t.y, acc[j]);
            }
        }
        #pragma unroll
        for (int j = 0; j < 8; j++) {
            const float2 r = unpack2(acc[j]);
            s_p2[hq * 1024 + (p0 + j) * 64 + c] = r.x + r.y;
        }
    }
    __syncthreads();

    // ---- softmax (warp = p): 4 partials + hpc, softmax over c, transposed store
    {
        const int p = warp;
        float v0 = g_hpc[p * C_ + lane];
        float v1 = g_hpc[p * C_ + 32 + lane];
        #pragma unroll
        for (int hq = 0; hq < 4; hq++) {
            v0 += s_p2[hq * 1024 + p * 64 + lane];
            v1 += s_p2[hq * 1024 + p * 64 + 32 + lane];
        }
        __syncthreads();   // all p2 reads done before mt (aliased) writes

        float mx = fmaxf(v0, v1);
        #pragma unroll
        for (int o = 16; o > 0; o >>= 1)
            mx = fmaxf(mx, __shfl_xor_sync(0xffffffffu, mx, o));
        const float e0 = __expf(v0 - mx);
        const float e1 = __expf(v1 - mx);
        float s = e0 + e1;
        #pragma unroll
        for (int o = 16; o > 0; o >>= 1)
            s += __shfl_xor_sync(0xffffffffu, s, o);
        const float inv = 1.f / s;
        s_mt[lane * 20 + p]        = e0 * inv;
        s_mt[(lane + 32) * 20 + p] = e1 * inv;

        if (tid == 0) {
            float S1 = 0.f, Sx = 0.f, Sr2 = 0.f, Sx2 = 0.f;
            #pragma unroll
            for (int w = 0; w < 16; w++) {
                S1 += s_red[w * 4 + 0]; Sx  += s_red[w * 4 + 1];
                Sr2 += s_red[w * 4 + 2]; Sx2 += s_red[w * 4 + 3];
            }
            const float invN = 1.f / 65536.f;
            #pragma unroll
            for (int g = 0; g < 2; g++) {
                const float A1 = g_gc[g * 4 + 0], A2 = g_gc[g * 4 + 1];
                const float B1 = g_gc[g * 4 + 2], B2 = g_gc[g * 4 + 3];
                const float mu = (A1 * S1 - A2 * Sx) * invN;
                const float E2 = (B1 * Sr2 + B2 * (Sx2 - Sr2)) * invN;
                s_grp[g * 2 + 0] = mu;
                s_grp[g * 2 + 1] = rsqrtf(E2 - mu * mu + EPS_);
            }
        }
    }
    __syncthreads();

    // ---- phase 4: out[p,h]; thread = (h, pb); x read directly from L1
    {
        const int h  = tid & 127;
        const int pb = tid >> 7;
        float c1[4], c2[4], c3[4];
        #pragma unroll
        for (int j = 0; j < 4; j++) {
            const int p = pb * 4 + j;
            const float4 pc = g_pc[p];
            const int g = p >> 3;
            const float mu = s_grp[g * 2 + 0];
            const float rs = s_grp[g * 2 + 1];
            const float gr = pc.z * rs;
            c1[j] = gr * pc.x;
            c2[j] = 1.f - gr * pc.y;
            c3[j] = pc.w - gr * mu;
        }
        u64 accR01 = 0, accR23 = 0, accX01 = 0, accX23 = 0;
        #pragma unroll 4
        for (int c = 0; c < C_; c++) {
            const float xv = xb[c * H_ + h];
            const float rv = fmaxf(xv, 0.f);
            const u64 rr = pack2(rv, rv);
            const u64 xx = pack2(xv, xv);
            const ulonglong2 mq = *(const ulonglong2*)(s_mt + c * 20 + pb * 4);
            accR01 = fma2(mq.x, rr, accR01);
            accR23 = fma2(mq.y, rr, accR23);
            accX01 = fma2(mq.x, xx, accX01);
            accX23 = fma2(mq.y, xx, accX23);
        }
        const float2 R01 = unpack2(accR01), R23 = unpack2(accR23);
        const float2 X01 = unpack2(accX01), X23 = unpack2(accX23);
        float* ob = out + (size_t)b * (P_ * H_);
        ob[(pb * 4 + 0) * H_ + h] = c1[0] * R01.x + c2[0] * X01.x + c3[0];
        ob[(pb * 4 + 1) * H_ + h] = c1[1] * R01.y + c2[1] * X01.y + c3[1];
        ob[(pb * 4 + 2) * H_ + h] = c1[2] * R23.x + c2[2] * X23.x + c3[2];
        ob[(pb * 4 + 3) * H_ + h] = c1[3] * R23.y + c2[3] * X23.y + c3[3];
    }
}

// ---------------- launch ----------------
extern "C" void kernel_launch(void* const* d_in, const int* in_sizes, int n_in,
                              void* d_out, int out_size)
{
    const float* x          = (const float*)d_in[0];
    const float* x_prompt   = (const float*)d_in[1];
    const float* emb_column = (const float*)d_in[2];
    const float* emb_prompt = (const float*)d_in[3];
    const float* lin_w      = (const float*)d_in[4];
    const float* lin_b      = (const float*)d_in[5];
    const float* ln_col_w   = (const float*)d_in[6];
    const float* ln_col_b   = (const float*)d_in[7];
    const float* ln_pr_w    = (const float*)d_in[8];
    const float* ln_pr_b    = (const float*)d_in[9];
    const float* expand_w   = (const float*)d_in[10];
    const float* gn_w       = (const float*)d_in[11];
    const float* gn_b       = (const float*)d_in[12];
    float* out = (float*)d_out;

    const int smemBytes = SM_FLOATS * (int)sizeof(float);   // 50,464 B
    cudaFuncSetAttribute(trompt_main_kernel,
                         cudaFuncAttributeMaxDynamicSharedMemorySize, smemBytes);

    setup_kernel<<<64, 256>>>(emb_column, emb_prompt, lin_w, lin_b,
                              ln_col_w, ln_col_b, ln_pr_w, ln_pr_b,
                              expand_w, gn_w, gn_b);
    trompt_main_kernel<<<B_, 512, smemBytes>>>(x, x_prompt, out);
}

// round 10
// speedup vs baseline: 1.3259x; 1.0137x over previous
#include <cuda_runtime.h>
#include <math.h>

#define B_ 512
#define C_ 64
#define H_ 128
#define P_ 16
#define G_ 2
#define EPS_ 1e-5f

typedef unsigned long long u64;

__device__ __forceinline__ u64 fma2(u64 a, u64 b, u64 c) {
    u64 d;
    asm("fma.rn.f32x2 %0, %1, %2, %3;" : "=l"(d) : "l"(a), "l"(b), "l"(c));
    return d;
}
__device__ __forceinline__ u64 pack2(float lo, float hi) {
    u64 d; asm("mov.b64 %0, {%1, %2};" : "=l"(d) : "f"(lo), "f"(hi)); return d;
}
__device__ __forceinline__ float2 unpack2(u64 v) {
    float2 r; asm("mov.b64 {%0, %1}, %2;" : "=f"(r.x), "=f"(r.y) : "l"(v)); return r;
}

// ---------------- device scratch ----------------
__device__ float  g_F[C_ * H_];       // F[c][k] = ec[c][k] + sum_h W2[h][k]*ec[c][h]
__device__ float  g_hpc[P_ * C_];     // hpc[p][c]
__device__ float4 g_pc[P_];           // {|w|, max(-w,0), gn_w, gn_b}
__device__ float  g_gc[2 * 4];        // per-group {A1,A2,B1,B2}

// ---------------- K1: setup kernel (64 blocks = c, 256 threads) ----------------
__global__ __launch_bounds__(256)
void setup_kernel(const float* __restrict__ emb_column,
                  const float* __restrict__ emb_prompt,
                  const float* __restrict__ lin_w,
                  const float* __restrict__ lin_b,
                  const float* __restrict__ ln_col_w,
                  const float* __restrict__ ln_col_b,
                  const float* __restrict__ ln_pr_w,
                  const float* __restrict__ ln_pr_b,
                  const float* __restrict__ expand_weight,
                  const float* __restrict__ gn_w,
                  const float* __restrict__ gn_b)
{
    __shared__ float s_ec[H_];
    __shared__ float s_ep[P_][H_];
    __shared__ float s_G1[H_];

    const int c    = blockIdx.x;
    const int tid  = threadIdx.x;
    const int warp = tid >> 5;
    const int lane = tid & 31;

    if (warp == 0) {
        const float* src = emb_column + c * H_;
        float v[4]; float s = 0.f, ss = 0.f;
        #pragma unroll
        for (int i = 0; i < 4; i++) { v[i] = src[lane + 32 * i]; s += v[i]; ss += v[i] * v[i]; }
        #pragma unroll
        for (int o = 16; o > 0; o >>= 1) {
            s  += __shfl_xor_sync(0xffffffffu, s,  o);
            ss += __shfl_xor_sync(0xffffffffu, ss, o);
        }
        const float mu  = s * (1.f / H_);
        const float inv = rsqrtf(ss * (1.f / H_) - mu * mu + EPS_);
        #pragma unroll
        for (int i = 0; i < 4; i++) {
            const int hh = lane + 32 * i;
            s_ec[hh] = (v[i] - mu) * inv * ln_col_w[hh] + ln_col_b[hh];
        }
    }
    #pragma unroll
    for (int rr = 0; rr < 2; rr++) {
        const int r = warp + rr * 8;
        const float* src = emb_prompt + r * H_;
        float v[4]; float s = 0.f, ss = 0.f;
        #pragma unroll
        for (int i = 0; i < 4; i++) { v[i] = src[lane + 32 * i]; s += v[i]; ss += v[i] * v[i]; }
        #pragma unroll
        for (int o = 16; o > 0; o >>= 1) {
            s  += __shfl_xor_sync(0xffffffffu, s,  o);
            ss += __shfl_xor_sync(0xffffffffu, ss, o);
        }
        const float mu  = s * (1.f / H_);
        const float inv = rsqrtf(ss * (1.f / H_) - mu * mu + EPS_);
        #pragma unroll
        for (int i = 0; i < 4; i++) {
            const int hh = lane + 32 * i;
            s_ep[r][hh] = (v[i] - mu) * inv * ln_pr_w[hh] + ln_pr_b[hh];
        }
    }
    __syncthreads();

    // G1 / F with deep unroll (MLP=16)
    {
        const int k     = tid & 127;
        const int which = tid >> 7;
        const float* base = lin_w + which * H_ + k;
        float acc = 0.f;
        #pragma unroll
        for (int hb = 0; hb < H_; hb += 16) {
            float w[16];
            #pragma unroll
            for (int i = 0; i < 16; i++)
                w[i] = base[(hb + i) * (2 * H_)];
            #pragma unroll
            for (int i = 0; i < 16; i++)
                acc += w[i] * s_ec[hb + i];
        }
        if (which == 0) s_G1[k] = acc;
        else            g_F[c * H_ + k] = acc + s_ec[k];
    }
    __syncthreads();

    #pragma unroll
    for (int rr = 0; rr < 2; rr++) {
        const int p = warp + rr * 8;
        float a = 0.f;
        #pragma unroll
        for (int i = 0; i < 4; i++) {
            const int hh = lane + 32 * i;
            const float e = s_ep[p][hh];
            a += (lin_b[hh] + e) * s_ec[hh] + e * s_G1[hh];
        }
        #pragma unroll
        for (int o = 16; o > 0; o >>= 1)
            a += __shfl_xor_sync(0xffffffffu, a, o);
        if (lane == 0) g_hpc[p * C_ + c] = a;
    }

    if (c == 0 && tid == 0) {
        #pragma unroll
        for (int p = 0; p < P_; p++) {
            const float w = expand_weight[p];
            g_pc[p] = make_float4(fabsf(w), fmaxf(-w, 0.f), gn_w[p], gn_b[p]);
        }
        for (int g = 0; g < 2; g++) {
            float A1 = 0.f, A2 = 0.f, B1 = 0.f, B2 = 0.f;
            for (int p = g * 8; p < g * 8 + 8; p++) {
                const float w  = expand_weight[p];
                const float aw = fabsf(w);
                const float v  = fmaxf(-w, 0.f);
                const float u  = aw - v;
                A1 += aw; A2 += v; B1 += u * u; B2 += v * v;
            }
            g_gc[g * 4 + 0] = A1; g_gc[g * 4 + 1] = A2;
            g_gc[g * 4 + 2] = B1; g_gc[g * 4 + 3] = B2;
        }
    }
}

// ---------------- K2: fused per-batch kernel (512 blocks, 256 threads, 4/SM) --------
// smem (floats): F[64x132] | m[16][64] | mt[64x20] | red[32] | grp[8]
#define SM_F     0                        // 8448
#define SM_M     (64 * 132)               // 1024
#define SM_MT    (SM_M + 16 * 64)         // 1280
#define SM_RED   (SM_MT + 64 * 20)        // 32
#define SM_GRP   (SM_RED + 32)            // 8
#define SM_FLOATS (SM_GRP + 8)            // 10792 floats = 43,168 B

extern __shared__ float sm[];

__global__ void __launch_bounds__(256, 4)
trompt_main_kernel(const float* __restrict__ x,
                   const float* __restrict__ x_prompt,
                   float* __restrict__ out)
{
    float* s_F   = sm + SM_F;
    float* s_m   = sm + SM_M;
    float* s_mt  = sm + SM_MT;
    float* s_red = sm + SM_RED;
    float* s_grp = sm + SM_GRP;

    const int tid  = threadIdx.x;
    const int b    = blockIdx.x;
    const int warp = tid >> 5;
    const int lane = tid & 31;
    const float* xb = x + (size_t)b * (C_ * H_);

    // ---- F staging + batch stats over x (x stays in L1)
    {
        float s1 = 0.f, sx = 0.f, sr2 = 0.f, sx2 = 0.f;
        const float4* xb4 = (const float4*)xb;
        #pragma unroll
        for (int i = 0; i < 8; i++) {
            const float4 v = xb4[tid + i * 256];
            float vv[4] = {v.x, v.y, v.z, v.w};
            #pragma unroll
            for (int q = 0; q < 4; q++) {
                const float r = fmaxf(vv[q], 0.f);
                s1 += r; sx += vv[q]; sr2 += r * r; sx2 += vv[q] * vv[q];
            }
        }
        const float4* f4 = (const float4*)g_F;
        #pragma unroll
        for (int i = 0; i < 8; i++) {
            const int e = tid + i * 256;
            const float4 v = f4[e];
            const int idx = e * 4;
            *(float4*)(s_F + (idx >> 7) * 132 + (idx & 127)) = v;
        }

        #pragma unroll
        for (int o = 16; o > 0; o >>= 1) {
            s1  += __shfl_xor_sync(0xffffffffu, s1,  o);
            sx  += __shfl_xor_sync(0xffffffffu, sx,  o);
            sr2 += __shfl_xor_sync(0xffffffffu, sr2, o);
            sx2 += __shfl_xor_sync(0xffffffffu, sx2, o);
        }
        if (lane == 0) {
            s_red[warp * 4 + 0] = s1;  s_red[warp * 4 + 1] = sx;
            s_red[warp * 4 + 2] = sr2; s_red[warp * 4 + 3] = sx2;
        }
    }
    __syncthreads();

    // ---- phase M: m[p,c] = hpc + xp @ F^T ; thread = (c, pg of 4p), full h loop
    {
        const int c  = tid & 63;
        const int pg = tid >> 6;     // 0..3
        const int p0 = pg * 4;
        const float* xpg = x_prompt + (size_t)b * (P_ * H_);
        u64 acc[4] = {0,0,0,0};
        #pragma unroll 8
        for (int hh = 0; hh < H_; hh += 4) {
            const ulonglong2 e = *(const ulonglong2*)(s_F + c * 132 + hh);
            #pragma unroll
            for (int j = 0; j < 4; j++) {
                const ulonglong2 t = *(const ulonglong2*)(xpg + (p0 + j) * H_ + hh);
                acc[j] = fma2(e.x, t.x, acc[j]);
                acc[j] = fma2(e.y, t.y, acc[j]);
            }
        }
        #pragma unroll
        for (int j = 0; j < 4; j++) {
            const float2 r = unpack2(acc[j]);
            s_m[(p0 + j) * 64 + c] = r.x + r.y + g_hpc[(p0 + j) * C_ + c];
        }
    }
    __syncthreads();

    // ---- softmax: warp w handles p = w, w+8; transposed store to s_mt
    #pragma unroll
    for (int rr = 0; rr < 2; rr++) {
        const int p = warp + rr * 8;
        const float v0 = s_m[p * 64 + lane];
        const float v1 = s_m[p * 64 + 32 + lane];
        float mx = fmaxf(v0, v1);
        #pragma unroll
        for (int o = 16; o > 0; o >>= 1)
            mx = fmaxf(mx, __shfl_xor_sync(0xffffffffu, mx, o));
        const float e0 = __expf(v0 - mx);
        const float e1 = __expf(v1 - mx);
        float s = e0 + e1;
        #pragma unroll
        for (int o = 16; o > 0; o >>= 1)
            s += __shfl_xor_sync(0xffffffffu, s, o);
        const float inv = 1.f / s;
        s_mt[lane * 20 + p]        = e0 * inv;
        s_mt[(lane + 32) * 20 + p] = e1 * inv;
    }
    if (tid == 0) {
        float S1 = 0.f, Sx = 0.f, Sr2 = 0.f, Sx2 = 0.f;
        #pragma unroll
        for (int w = 0; w < 8; w++) {
            S1 += s_red[w * 4 + 0]; Sx  += s_red[w * 4 + 1];
            Sr2 += s_red[w * 4 + 2]; Sx2 += s_red[w * 4 + 3];
        }
        const float invN = 1.f / 65536.f;
        #pragma unroll
        for (int g = 0; g < 2; g++) {
            const float A1 = g_gc[g * 4 + 0], A2 = g_gc[g * 4 + 1];
            const float B1 = g_gc[g * 4 + 2], B2 = g_gc[g * 4 + 3];
            const float mu = (A1 * S1 - A2 * Sx) * invN;
            const float E2 = (B1 * Sr2 + B2 * (Sx2 - Sr2)) * invN;
            s_grp[g * 2 + 0] = mu;
            s_grp[g * 2 + 1] = rsqrtf(E2 - mu * mu + EPS_);
        }
    }
    __syncthreads();

    // ---- phase 4: thread = (h, pb of 8p); coefficients applied AFTER the loop
    {
        const int h  = tid & 127;
        const int pb = tid >> 7;     // 0..1, p = pb*8 + j
        u64 aR[4] = {0,0,0,0}, aX[4] = {0,0,0,0};
        #pragma unroll 4
        for (int c = 0; c < C_; c++) {
            const float xv = xb[c * H_ + h];
            const float rv = fmaxf(xv, 0.f);
            const u64 rr = pack2(rv, rv);
            const u64 xx = pack2(xv, xv);
            const ulonglong2 m01 = *(const ulonglong2*)(s_mt + c * 20 + pb * 8);
            const ulonglong2 m23 = *(const ulonglong2*)(s_mt + c * 20 + pb * 8 + 4);
            aR[0] = fma2(m01.x, rr, aR[0]);
            aR[1] = fma2(m01.y, rr, aR[1]);
            aR[2] = fma2(m23.x, rr, aR[2]);
            aR[3] = fma2(m23.y, rr, aR[3]);
            aX[0] = fma2(m01.x, xx, aX[0]);
            aX[1] = fma2(m01.y, xx, aX[1]);
            aX[2] = fma2(m23.x, xx, aX[2]);
            aX[3] = fma2(m23.y, xx, aX[3]);
        }
        float* ob = out + (size_t)b * (P_ * H_);
        #pragma unroll
        for (int q = 0; q < 4; q++) {
            const float2 R = unpack2(aR[q]);
            const float2 X = unpack2(aX[q]);
            #pragma unroll
            for (int half = 0; half < 2; half++) {
                const int p = pb * 8 + q * 2 + half;
                const float4 pc = g_pc[p];
                const int g = p >> 3;
                const float mu = s_grp[g * 2 + 0];
                const float rs = s_grp[g * 2 + 1];
                const float gr = pc.z * rs;
                const float c1 = gr * pc.x;
                const float c2 = 1.f - gr * pc.y;
                const float c3 = pc.w - gr * mu;
                const float Rv = half ? R.y : R.x;
                const float Xv = half ? X.y : X.x;
                ob[p * H_ + h] = c1 * Rv + c2 * Xv + c3;
            }
        }
    }
}

// ---------------- launch ----------------
extern "C" void kernel_launch(void* const* d_in, const int* in_sizes, int n_in,
                              void* d_out, int out_size)
{
    const float* x          = (const float*)d_in[0];
    const float* x_prompt   = (const float*)d_in[1];
    const float* emb_column = (const float*)d_in[2];
    const float* emb_prompt = (const float*)d_in[3];
    const float* lin_w      = (const float*)d_in[4];
    const float* lin_b      = (const float*)d_in[5];
    const float* ln_col_w   = (const float*)d_in[6];
    const float* ln_col_b   = (const float*)d_in[7];
    const float* ln_pr_w    = (const float*)d_in[8];
    const float* ln_pr_b    = (const float*)d_in[9];
    const float* expand_w   = (const float*)d_in[10];
    const float* gn_w       = (const float*)d_in[11];
    const float* gn_b       = (const float*)d_in[12];
    float* out = (float*)d_out;

    const int smemBytes = SM_FLOATS * (int)sizeof(float);   // 43,168 B
    cudaFuncSetAttribute(trompt_main_kernel,
                         cudaFuncAttributeMaxDynamicSharedMemorySize, smemBytes);

    setup_kernel<<<64, 256>>>(emb_column, emb_prompt, lin_w, lin_b,
                              ln_col_w, ln_col_b, ln_pr_w, ln_pr_b,
                              expand_w, gn_w, gn_b);
    trompt_main_kernel<<<B_, 256, smemBytes>>>(x, x_prompt, out);
}

// round 11
// speedup vs baseline: 1.3811x; 1.0417x over previous
#include <cuda_runtime.h>
#include <math.h>

#define B_ 512
#define C_ 64
#define H_ 128
#define P_ 16
#define G_ 2
#define EPS_ 1e-5f

typedef unsigned long long u64;

__device__ __forceinline__ u64 fma2(u64 a, u64 b, u64 c) {
    u64 d;
    asm("fma.rn.f32x2 %0, %1, %2, %3;" : "=l"(d) : "l"(a), "l"(b), "l"(c));
    return d;
}
__device__ __forceinline__ u64 pack2(float lo, float hi) {
    u64 d; asm("mov.b64 %0, {%1, %2};" : "=l"(d) : "f"(lo), "f"(hi)); return d;
}
__device__ __forceinline__ float2 unpack2(u64 v) {
    float2 r; asm("mov.b64 {%0, %1}, %2;" : "=f"(r.x), "=f"(r.y) : "l"(v)); return r;
}

// ---------------- device scratch ----------------
__device__ float  g_F[C_ * H_];       // F[c][k] = ec[c][k] + sum_h W2[h][k]*ec[c][h]
__device__ float  g_hpc[P_ * C_];     // hpc[p][c]
__device__ float4 g_pc[P_];           // {|w|, max(-w,0), gn_w, gn_b}
__device__ float  g_gc[2 * 4];        // per-group {A1,A2,B1,B2}

// ---------------- K1: setup kernel (64 blocks = c, 256 threads) ----------------
__global__ __launch_bounds__(256)
void setup_kernel(const float* __restrict__ emb_column,
                  const float* __restrict__ emb_prompt,
                  const float* __restrict__ lin_w,
                  const float* __restrict__ lin_b,
                  const float* __restrict__ ln_col_w,
                  const float* __restrict__ ln_col_b,
                  const float* __restrict__ ln_pr_w,
                  const float* __restrict__ ln_pr_b,
                  const float* __restrict__ expand_weight,
                  const float* __restrict__ gn_w,
                  const float* __restrict__ gn_b)
{
    __shared__ float s_ec[H_];
    __shared__ float s_ep[P_][H_];
    __shared__ float s_G1[H_];

    const int c    = blockIdx.x;
    const int tid  = threadIdx.x;
    const int warp = tid >> 5;
    const int lane = tid & 31;

    if (warp == 0) {
        const float* src = emb_column + c * H_;
        float v[4]; float s = 0.f, ss = 0.f;
        #pragma unroll
        for (int i = 0; i < 4; i++) { v[i] = src[lane + 32 * i]; s += v[i]; ss += v[i] * v[i]; }
        #pragma unroll
        for (int o = 16; o > 0; o >>= 1) {
            s  += __shfl_xor_sync(0xffffffffu, s,  o);
            ss += __shfl_xor_sync(0xffffffffu, ss, o);
        }
        const float mu  = s * (1.f / H_);
        const float inv = rsqrtf(ss * (1.f / H_) - mu * mu + EPS_);
        #pragma unroll
        for (int i = 0; i < 4; i++) {
            const int hh = lane + 32 * i;
            s_ec[hh] = (v[i] - mu) * inv * ln_col_w[hh] + ln_col_b[hh];
        }
    }
    #pragma unroll
    for (int rr = 0; rr < 2; rr++) {
        const int r = warp + rr * 8;
        const float* src = emb_prompt + r * H_;
        float v[4]; float s = 0.f, ss = 0.f;
        #pragma unroll
        for (int i = 0; i < 4; i++) { v[i] = src[lane + 32 * i]; s += v[i]; ss += v[i] * v[i]; }
        #pragma unroll
        for (int o = 16; o > 0; o >>= 1) {
            s  += __shfl_xor_sync(0xffffffffu, s,  o);
            ss += __shfl_xor_sync(0xffffffffu, ss, o);
        }
        const float mu  = s * (1.f / H_);
        const float inv = rsqrtf(ss * (1.f / H_) - mu * mu + EPS_);
        #pragma unroll
        for (int i = 0; i < 4; i++) {
            const int hh = lane + 32 * i;
            s_ep[r][hh] = (v[i] - mu) * inv * ln_pr_w[hh] + ln_pr_b[hh];
        }
    }
    __syncthreads();

    // G1 / F with deep unroll (MLP=16)
    {
        const int k     = tid & 127;
        const int which = tid >> 7;
        const float* base = lin_w + which * H_ + k;
        float acc = 0.f;
        #pragma unroll
        for (int hb = 0; hb < H_; hb += 16) {
            float w[16];
            #pragma unroll
            for (int i = 0; i < 16; i++)
                w[i] = base[(hb + i) * (2 * H_)];
            #pragma unroll
            for (int i = 0; i < 16; i++)
                acc += w[i] * s_ec[hb + i];
        }
        if (which == 0) s_G1[k] = acc;
        else            g_F[c * H_ + k] = acc + s_ec[k];
    }
    __syncthreads();

    #pragma unroll
    for (int rr = 0; rr < 2; rr++) {
        const int p = warp + rr * 8;
        float a = 0.f;
        #pragma unroll
        for (int i = 0; i < 4; i++) {
            const int hh = lane + 32 * i;
            const float e = s_ep[p][hh];
            a += (lin_b[hh] + e) * s_ec[hh] + e * s_G1[hh];
        }
        #pragma unroll
        for (int o = 16; o > 0; o >>= 1)
            a += __shfl_xor_sync(0xffffffffu, a, o);
        if (lane == 0) g_hpc[p * C_ + c] = a;
    }

    if (c == 0 && tid == 0) {
        #pragma unroll
        for (int p = 0; p < P_; p++) {
            const float w = expand_weight[p];
            g_pc[p] = make_float4(fabsf(w), fmaxf(-w, 0.f), gn_w[p], gn_b[p]);
        }
        for (int g = 0; g < 2; g++) {
            float A1 = 0.f, A2 = 0.f, B1 = 0.f, B2 = 0.f;
            for (int p = g * 8; p < g * 8 + 8; p++) {
                const float w  = expand_weight[p];
                const float aw = fabsf(w);
                const float v  = fmaxf(-w, 0.f);
                const float u  = aw - v;
                A1 += aw; A2 += v; B1 += u * u; B2 += v * v;
            }
            g_gc[g * 4 + 0] = A1; g_gc[g * 4 + 1] = A2;
            g_gc[g * 4 + 2] = B1; g_gc[g * 4 + 3] = B2;
        }
    }
}

// ---------------- K2: fused per-batch kernel (512 blocks, 256 threads, 4/SM) --------
// smem (floats): F[64x132] | m[16][64] | mt[64x20] | red[16] | grp[8]
#define SM_F     0                        // 8448
#define SM_M     (64 * 132)               // 1024
#define SM_MT    (SM_M + 16 * 64)         // 1280
#define SM_RED   (SM_MT + 64 * 20)        // 16
#define SM_GRP   (SM_RED + 16)            // 8
#define SM_FLOATS (SM_GRP + 8)            // 10776 floats = 43,104 B

extern __shared__ float sm[];

__global__ void __launch_bounds__(256, 4)
trompt_main_kernel(const float* __restrict__ x,
                   const float* __restrict__ x_prompt,
                   float* __restrict__ out)
{
    float* s_F   = sm + SM_F;
    float* s_m   = sm + SM_M;
    float* s_mt  = sm + SM_MT;
    float* s_red = sm + SM_RED;
    float* s_grp = sm + SM_GRP;

    const int tid  = threadIdx.x;
    const int b    = blockIdx.x;
    const int warp = tid >> 5;
    const int lane = tid & 31;
    const float* xb = x + (size_t)b * (C_ * H_);

    // ---- F staging only (x is NOT pre-read; stats fused into phase 4)
    {
        const float4* f4 = (const float4*)g_F;
        #pragma unroll
        for (int i = 0; i < 8; i++) {
            const int e = tid + i * 256;
            const float4 v = f4[e];
            const int idx = e * 4;
            *(float4*)(s_F + (idx >> 7) * 132 + (idx & 127)) = v;
        }
    }
    __syncthreads();

    // ---- phase M: m[p,c] = hpc + xp @ F^T ; thread = (c, pg of 4p), full h loop
    {
        const int c  = tid & 63;
        const int pg = tid >> 6;     // 0..3
        const int p0 = pg * 4;
        const float* xpg = x_prompt + (size_t)b * (P_ * H_);
        u64 acc[4] = {0,0,0,0}, accB[4] = {0,0,0,0};
        #pragma unroll 8
        for (int hh = 0; hh < H_; hh += 4) {
            const ulonglong2 e = *(const ulonglong2*)(s_F + c * 132 + hh);
            #pragma unroll
            for (int j = 0; j < 4; j++) {
                const ulonglong2 t = *(const ulonglong2*)(xpg + (p0 + j) * H_ + hh);
                acc[j]  = fma2(e.x, t.x, acc[j]);
                accB[j] = fma2(e.y, t.y, accB[j]);
            }
        }
        #pragma unroll
        for (int j = 0; j < 4; j++) {
            const float2 r  = unpack2(acc[j]);
            const float2 r2 = unpack2(accB[j]);
            s_m[(p0 + j) * 64 + c] = (r.x + r.y) + (r2.x + r2.y) + g_hpc[(p0 + j) * C_ + c];
        }
    }
    __syncthreads();

    // ---- softmax: warp w handles p = w, w+8; transposed store to s_mt
    #pragma unroll
    for (int rr = 0; rr < 2; rr++) {
        const int p = warp + rr * 8;
        const float v0 = s_m[p * 64 + lane];
        const float v1 = s_m[p * 64 + 32 + lane];
        float mx = fmaxf(v0, v1);
        #pragma unroll
        for (int o = 16; o > 0; o >>= 1)
            mx = fmaxf(mx, __shfl_xor_sync(0xffffffffu, mx, o));
        const float e0 = __expf(v0 - mx);
        const float e1 = __expf(v1 - mx);
        float s = e0 + e1;
        #pragma unroll
        for (int o = 16; o > 0; o >>= 1)
            s += __shfl_xor_sync(0xffffffffu, s, o);
        const float inv = 1.f / s;
        s_mt[lane * 20 + p]        = e0 * inv;
        s_mt[(lane + 32) * 20 + p] = e1 * inv;
    }
    __syncthreads();

    // ---- phase 4: accumulate Rm/Xm (+ fused stats on pb==0); thread = (h, pb of 8p)
    const int h  = tid & 127;
    const int pb = tid >> 7;     // 0..1, p = pb*8 + j; warp-uniform
    u64 aR[4] = {0,0,0,0}, aX[4] = {0,0,0,0};
    {
        float s1 = 0.f, sx = 0.f, sr2 = 0.f, sx2 = 0.f;
        #pragma unroll 8
        for (int c = 0; c < C_; c++) {
            const float xv = xb[c * H_ + h];
            const float rv = fmaxf(xv, 0.f);
            const u64 rr = pack2(rv, rv);
            const u64 xx = pack2(xv, xv);
            const ulonglong2 m01 = *(const ulonglong2*)(s_mt + c * 20 + pb * 8);
            const ulonglong2 m23 = *(const ulonglong2*)(s_mt + c * 20 + pb * 8 + 4);
            aR[0] = fma2(m01.x, rr, aR[0]);
            aR[1] = fma2(m01.y, rr, aR[1]);
            aR[2] = fma2(m23.x, rr, aR[2]);
            aR[3] = fma2(m23.y, rr, aR[3]);
            aX[0] = fma2(m01.x, xx, aX[0]);
            aX[1] = fma2(m01.y, xx, aX[1]);
            aX[2] = fma2(m23.x, xx, aX[2]);
            aX[3] = fma2(m23.y, xx, aX[3]);
            if (pb == 0) {            // warp-uniform predicate; each (c,h) counted once
                s1 += rv; sx += xv; sr2 += rv * rv; sx2 += xv * xv;
            }
        }
        if (pb == 0) {
            #pragma unroll
            for (int o = 16; o > 0; o >>= 1) {
                s1  += __shfl_xor_sync(0xffffffffu, s1,  o);
                sx  += __shfl_xor_sync(0xffffffffu, sx,  o);
                sr2 += __shfl_xor_sync(0xffffffffu, sr2, o);
                sx2 += __shfl_xor_sync(0xffffffffu, sx2, o);
            }
            if (lane == 0) {
                s_red[warp * 4 + 0] = s1;  s_red[warp * 4 + 1] = sx;
                s_red[warp * 4 + 2] = sr2; s_red[warp * 4 + 3] = sx2;
            }
        }
    }
    __syncthreads();

    if (tid == 0) {
        float S1 = 0.f, Sx = 0.f, Sr2 = 0.f, Sx2 = 0.f;
        #pragma unroll
        for (int w = 0; w < 4; w++) {
            S1 += s_red[w * 4 + 0]; Sx  += s_red[w * 4 + 1];
            Sr2 += s_red[w * 4 + 2]; Sx2 += s_red[w * 4 + 3];
        }
        const float invN = 1.f / 65536.f;
        #pragma unroll
        for (int g = 0; g < 2; g++) {
            const float A1 = g_gc[g * 4 + 0], A2 = g_gc[g * 4 + 1];
            const float B1 = g_gc[g * 4 + 2], B2 = g_gc[g * 4 + 3];
            const float mu = (A1 * S1 - A2 * Sx) * invN;
            const float E2 = (B1 * Sr2 + B2 * (Sx2 - Sr2)) * invN;
            s_grp[g * 2 + 0] = mu;
            s_grp[g * 2 + 1] = rsqrtf(E2 - mu * mu + EPS_);
        }
    }
    __syncthreads();

    // ---- apply coefficients + store
    {
        float* ob = out + (size_t)b * (P_ * H_);
        #pragma unroll
        for (int q = 0; q < 4; q++) {
            const float2 R = unpack2(aR[q]);
            const float2 X = unpack2(aX[q]);
            #pragma unroll
            for (int half = 0; half < 2; half++) {
                const int p = pb * 8 + q * 2 + half;
                const float4 pc = g_pc[p];
                const int g = p >> 3;
                const float mu = s_grp[g * 2 + 0];
                const float rs = s_grp[g * 2 + 1];
                const float gr = pc.z * rs;
                const float c1 = gr * pc.x;
                const float c2 = 1.f - gr * pc.y;
                const float c3 = pc.w - gr * mu;
                const float Rv = half ? R.y : R.x;
                const float Xv = half ? X.y : X.x;
                ob[p * H_ + h] = c1 * Rv + c2 * Xv + c3;
            }
        }
    }
}

// ---------------- launch ----------------
extern "C" void kernel_launch(void* const* d_in, const int* in_sizes, int n_in,
                              void* d_out, int out_size)
{
    const float* x          = (const float*)d_in[0];
    const float* x_prompt   = (const float*)d_in[1];
    const float* emb_column = (const float*)d_in[2];
    const float* emb_prompt = (const float*)d_in[3];
    const float* lin_w      = (const float*)d_in[4];
    const float* lin_b      = (const float*)d_in[5];
    const float* ln_col_w   = (const float*)d_in[6];
    const float* ln_col_b   = (const float*)d_in[7];
    const float* ln_pr_w    = (const float*)d_in[8];
    const float* ln_pr_b    = (const float*)d_in[9];
    const float* expand_w   = (const float*)d_in[10];
    const float* gn_w       = (const float*)d_in[11];
    const float* gn_b       = (const float*)d_in[12];
    float* out = (float*)d_out;

    const int smemBytes = SM_FLOATS * (int)sizeof(float);   // 43,104 B
    cudaFuncSetAttribute(trompt_main_kernel,
                         cudaFuncAttributeMaxDynamicSharedMemorySize, smemBytes);

    setup_kernel<<<64, 256>>>(emb_column, emb_prompt, lin_w, lin_b,
                              ln_col_w, ln_col_b, ln_pr_w, ln_pr_b,
                              expand_w, gn_w, gn_b);
    trompt_main_kernel<<<B_, 256, smemBytes>>>(x, x_prompt, out);
}